// round 5
// baseline (speedup 1.0000x reference)
#include <cuda_runtime.h>

// Problem constants (match reference)
#define NUM_CH   5
#define CROP_LO  70      // D//2 - 16, D = 173
#define CROP_HI  101     // CROP_LO + 32 - 1
#define CROP_N   32
#define CUBES    5
#define LATO     11      // 2*CUBES+1
#define RES2     0.0625f // RES*RES

// Monotonic arrive counter for the software grid barrier. Never reset: every
// launch adds exactly gridDim.x, so each launch's release target is
// base + gridDim.x, derived from the ticket. Work and output are identical
// on every call.
__device__ unsigned int g_barrier_cnt = 0;

// ONE kernel, one graph node. Grid is sized <= 148 blocks so all CTAs are
// co-resident -> device-wide spin barrier is deadlock-free.
// Phase A: grid-stride zero of the output. Phase B: global barrier.
// Phase C: warp-per-atom Gaussian scatter with global RED adds (R2 body).
__global__ void __launch_bounds__(128) fused_voxelize_kernel(
    const float* __restrict__ coords,        // [B, N, 3]
    const int*   __restrict__ atoms_channel, // [B, N]
    const float* __restrict__ radius,        // [B, N]
    float* __restrict__ out,                 // [B, NUM_CH, 32, 32, 32]
    int n_per_batch, int n_atoms, int out_elems)
{
    const int tid = threadIdx.x;

    // --- Phase A: zero the output (grid-stride float4) ---
    float4* o4 = (float4*)out;
    const int n4 = out_elems >> 2;
    const int gstride = gridDim.x * blockDim.x;
    for (int i = blockIdx.x * blockDim.x + tid; i < n4; i += gstride)
        o4[i] = make_float4(0.f, 0.f, 0.f, 0.f);
    __threadfence();   // make zeros visible at L2 before releasing the barrier

    // --- Phase B: device-wide software barrier (all CTAs co-resident) ---
    __shared__ unsigned s_target;
    __syncthreads();
    if (tid == 0) {
        unsigned t = atomicAdd(&g_barrier_cnt, 1u);
        s_target = t - (t % gridDim.x) + gridDim.x;  // this launch's release count
    }
    __syncthreads();
    if (tid == 0) {
        while (*(volatile unsigned*)&g_barrier_cnt < s_target) { }
    }
    __syncthreads();
    __threadfence();   // acquire: zeros from all blocks visible before atomics

    // --- Phase C: warp-per-atom splat (proven R2 body) ---
    const int warp_g = (blockIdx.x * blockDim.x + tid) >> 5;
    const int lane   = tid & 31;
    const int total_warps = gstride >> 5;

    for (int atom = warp_g; atom < n_atoms; atom += total_warps) {
        const int b = atom / n_per_batch;

        const float cx = coords[3 * atom + 0];
        const float cy = coords[3 * atom + 1];
        const float cz = coords[3 * atom + 2];
        const float r  = radius[atom];
        const int   ch = atoms_channel[atom];

        // scaled = (c + BOX)/RES + (CUBES+1); /0.25 == *4 exactly
        const float sx = (cx + 20.0f) * 4.0f + 6.0f;
        const float sy = (cy + 20.0f) * 4.0f + 6.0f;
        const float sz = (cz + 20.0f) * 4.0f + 6.0f;
        const int bx = (int)floorf(sx) - CUBES;
        const int by = (int)floorf(sy) - CUBES;
        const int bz = (int)floorf(sz) - CUBES;

        // Clip splat box against crop window [CROP_LO, CROP_HI]
        const int x0 = max(0, CROP_LO - bx), x1 = min(LATO - 1, CROP_HI - bx);
        const int y0 = max(0, CROP_LO - by), y1 = min(LATO - 1, CROP_HI - by);
        const int z0 = max(0, CROP_LO - bz), z1 = min(LATO - 1, CROP_HI - bz);
        const int nx = x1 - x0 + 1, ny = y1 - y0 + 1, nz = z1 - z0 + 1;
        if (nx <= 0 || ny <= 0 || nz <= 0) continue;

        const float coef = 0.5f * RES2 / (r * r);
        const float fx = sx - (float)(bx + x0) - 0.5f;
        const float fy = sy - (float)(by + y0) - 0.5f;
        const float fz = sz - (float)(bz + z0) - 0.5f;

        const int nyz  = ny * nz;
        const int ntot = nx * nyz;
        const float rnyz = 1.0f / (float)nyz;
        const float rnz  = 1.0f / (float)nz;

        float* __restrict__ outp = out
            + (size_t)(b * NUM_CH + ch) * (CROP_N * CROP_N * CROP_N)
            + ((bx + x0 - CROP_LO) * CROP_N + (by + y0 - CROP_LO)) * CROP_N
            + (bz + z0 - CROP_LO);

        for (int k = lane; k < ntot; k += 32) {
            // exact small-int division via fp32 (k < 1331, divisors <= 121)
            int ox  = (int)(((float)k + 0.5f) * rnyz);
            int rem = k - ox * nyz;
            int oy  = (int)(((float)rem + 0.5f) * rnz);
            int oz  = rem - oy * nz;
            float dx = fx - (float)ox;
            float dy = fy - (float)oy;
            float dz = fz - (float)oz;
            float d2 = fmaf(dx, dx, fmaf(dy, dy, dz * dz));
            float v  = __expf(-coef * d2);
            atomicAdd(&outp[(ox * CROP_N + oy) * CROP_N + oz], v);
        }
    }
}

extern "C" void kernel_launch(void* const* d_in, const int* in_sizes, int n_in,
                              void* d_out, int out_size) {
    const float* coords        = (const float*)d_in[0]; // [B,N,3]
    const int*   atoms_channel = (const int*)d_in[1];   // [B,N]
    const float* radius        = (const float*)d_in[2]; // [B,N]
    float* out = (float*)d_out;

    int n_atoms = in_sizes[1];                               // B*N = 512
    int B = out_size / (NUM_CH * CROP_N * CROP_N * CROP_N);  // 8
    int n_per_batch = n_atoms / B;                           // 64

    // 4 warps/block; cap grid at 148 so all CTAs are co-resident (barrier safety)
    int blocks = (n_atoms + 3) / 4;   // one warp per atom
    if (blocks > 148) blocks = 148;   // falls back to warp-strided atom loop

    fused_voxelize_kernel<<<blocks, 128>>>(coords, atoms_channel, radius, out,
                                           n_per_batch, n_atoms, out_size);
}

// round 6
// speedup vs baseline: 2.6827x; 2.6827x over previous
#include <cuda_runtime.h>

// Problem constants (match reference)
#define NUM_CH   5
#define CROP_LO  70      // D//2 - 16, D = 173
#define CROP_HI  101     // CROP_LO + 32 - 1
#define CROP_N   32
#define CUBES    5
#define LATO     11      // 2*CUBES+1
#define RES2     0.0625f // RES*RES

#define SLABS    3       // x-slabs of width 11,11,10 -> 40*3 = 120 blocks <= 148
#define MAX_N    256     // max atoms per batch supported

// ONE kernel, one graph node. Each block exclusively owns one
// (batch, channel, x-slab) region of the output, so zero->splat needs only
// __syncthreads (block-scope ordering of its own STG zeros vs its own REDs).
// Splat work is cell-parallel across ALL 256 threads per atom (max 6 inner
// iterations/thread/atom) -> no barrier-coupled warp imbalance.
__global__ void __launch_bounds__(256) fused_voxelize_kernel(
    const float* __restrict__ coords,        // [B, N, 3]
    const int*   __restrict__ atoms_channel, // [B, N]
    const float* __restrict__ radius,        // [B, N]
    float* __restrict__ out,                 // [B, NUM_CH, 32, 32, 32]
    int n_per_batch)
{
    __shared__ int   s_cnt;
    __shared__ int   s_ntot[MAX_N];
    __shared__ int   s_nyz[MAX_N], s_nz[MAX_N];
    __shared__ float s_rnyz[MAX_N], s_rnz[MAX_N];
    __shared__ float s_fx[MAX_N], s_fy[MAX_N], s_fz[MAX_N];
    __shared__ float s_coef[MAX_N];
    __shared__ int   s_off[MAX_N];

    const int tid  = threadIdx.x;
    const int bc   = blockIdx.x;          // b * NUM_CH + ch  (0..39)
    const int slab = blockIdx.y;          // 0..2
    const int b    = bc / NUM_CH;
    const int ch   = bc - b * NUM_CH;

    const int xs    = slab * 11;                    // slab x start (crop coords)
    const int xw    = (slab == 2) ? 10 : 11;        // slab width
    const int sx_lo = CROP_LO + xs;
    const int sx_hi = sx_lo + xw - 1;

    // --- preload atom data into registers (parallel, overlaps the zeroing) ---
    float cx = 0.f, cy = 0.f, cz = 0.f, r = 1.f;
    int   c  = -1;
    const bool has_atom = (tid < n_per_batch);
    if (has_atom) {
        const int atom = b * n_per_batch + tid;
        cx = coords[3 * atom + 0];
        cy = coords[3 * atom + 1];
        cz = coords[3 * atom + 2];
        r  = radius[atom];
        c  = atoms_channel[atom];
    }
    if (tid == 0) s_cnt = 0;

    // --- zero this block's exclusive global slab (contiguous, float4) ---
    float* vol = out + (size_t)bc * (CROP_N * CROP_N * CROP_N);
    float4* dst = (float4*)(vol + xs * (CROP_N * CROP_N));
    const int n4 = xw * (CROP_N * CROP_N / 4);      // 2816 or 2560
    for (int i = tid; i < n4; i += 256)
        dst[i] = make_float4(0.f, 0.f, 0.f, 0.f);

    __syncthreads();   // s_cnt init visible; zeros ordered before our REDs

    // --- derive + compact worklist (threads 0..n-1) ---
    if (has_atom && c == ch) {
        // scaled = (c + BOX)/RES + (CUBES+1); /0.25 == *4 exactly
        const float sx = (cx + 20.0f) * 4.0f + 6.0f;
        const float sy = (cy + 20.0f) * 4.0f + 6.0f;
        const float sz = (cz + 20.0f) * 4.0f + 6.0f;
        const int bx = (int)floorf(sx) - CUBES;
        const int by = (int)floorf(sy) - CUBES;
        const int bz = (int)floorf(sz) - CUBES;

        const int x0 = max(0, sx_lo  - bx), x1 = min(LATO - 1, sx_hi  - bx);
        const int y0 = max(0, CROP_LO - by), y1 = min(LATO - 1, CROP_HI - by);
        const int z0 = max(0, CROP_LO - bz), z1 = min(LATO - 1, CROP_HI - bz);
        const int nx = x1 - x0 + 1, ny = y1 - y0 + 1, nz = z1 - z0 + 1;

        if (nx > 0 && ny > 0 && nz > 0) {
            const int slot = atomicAdd(&s_cnt, 1);
            const int nyz = ny * nz;
            s_ntot[slot] = nx * nyz;
            s_nyz[slot]  = nyz;
            s_nz[slot]   = nz;
            s_rnyz[slot] = 1.0f / (float)nyz;
            s_rnz[slot]  = 1.0f / (float)nz;
            s_fx[slot]   = sx - (float)(bx + x0) - 0.5f;
            s_fy[slot]   = sy - (float)(by + y0) - 0.5f;
            s_fz[slot]   = sz - (float)(bz + z0) - 0.5f;
            s_coef[slot] = 0.5f * RES2 / (r * r);
            s_off[slot]  = ((bx + x0 - CROP_LO) * CROP_N + (by + y0 - CROP_LO)) * CROP_N
                           + (bz + z0 - CROP_LO);
        }
    }
    __syncthreads();

    // --- splat: sequential over worklist atoms, cell-parallel over 256 threads ---
    const int cnt = s_cnt;
    for (int i = 0; i < cnt; ++i) {
        const int   ntot = s_ntot[i];
        const int   nyz  = s_nyz[i],  nz  = s_nz[i];
        const float rnyz = s_rnyz[i], rnz = s_rnz[i];
        const float fx = s_fx[i], fy = s_fy[i], fz = s_fz[i];
        const float coef = s_coef[i];
        float* __restrict__ p = vol + s_off[i];

        for (int k = tid; k < ntot; k += 256) {
            // exact small-int division via fp32 (k < 1331, divisors <= 121)
            int ox  = (int)(((float)k + 0.5f) * rnyz);
            int rem = k - ox * nyz;
            int oy  = (int)(((float)rem + 0.5f) * rnz);
            int oz  = rem - oy * nz;
            float dx = fx - (float)ox;
            float dy = fy - (float)oy;
            float dz = fz - (float)oz;
            float d2 = fmaf(dx, dx, fmaf(dy, dy, dz * dz));
            float v  = __expf(-coef * d2);
            atomicAdd(&p[(ox * CROP_N + oy) * CROP_N + oz], v);
        }
    }
}

extern "C" void kernel_launch(void* const* d_in, const int* in_sizes, int n_in,
                              void* d_out, int out_size) {
    const float* coords        = (const float*)d_in[0]; // [B,N,3]
    const int*   atoms_channel = (const int*)d_in[1];   // [B,N]
    const float* radius        = (const float*)d_in[2]; // [B,N]
    float* out = (float*)d_out;

    int n_atoms = in_sizes[1];                               // B*N = 512
    int B = out_size / (NUM_CH * CROP_N * CROP_N * CROP_N);  // 8
    int n_per_batch = n_atoms / B;                           // 64

    dim3 grid(B * NUM_CH, SLABS);                            // 40 x 3 = 120 blocks
    fused_voxelize_kernel<<<grid, 256>>>(coords, atoms_channel, radius, out,
                                         n_per_batch);
}